// round 2
// baseline (speedup 1.0000x reference)
#include <cuda_runtime.h>
#include <math.h>

#define NP 200
#define NCLS 81
#define SCALE (1.0f/16.0f)

// ---------------- scratch (static device arrays; no allocations) ----------------
__device__ float d_featT[(size_t)256*256*256];          // 64 MB  (HWC)
__device__ float d_roi7 [(size_t)NP*256*49];            // 10 MB  (n,c,p)
__device__ float d_h1   [NP*1024];
__device__ float d_h2   [NP*1024];
__device__ float d_delt [NP*NCLS*4];
__device__ float d_logit[NP*NCLS];
__device__ float d_score[NP*NCLS];
__device__ float d_bests[NP];
__device__ float d_boxes[NP*4];
__device__ float d_keepf[NP];
__device__ float d_roi14[(size_t)NP*256*196];           // 40 MB
__device__ float d_m1   [(size_t)NP*256*784];           // 160 MB (n,c,28,28)
__device__ float d_m2   [(size_t)NP*256*3136];          // 642 MB (n,c,56,56)
__device__ float d_wr1  [4*256*256];                    // [ab][c][o]
__device__ float d_wr2  [4*256*256];
__device__ float d_wmT  [256*128];                      // [c][o] padded to 128

// ---------------- feature transpose: (C,H,W) -> (H*W, C) ----------------
__global__ void k_transpose(const float* __restrict__ f) {
    __shared__ float t[32][33];
    int x0 = blockIdx.x * 32, c0 = blockIdx.y * 32;
    int tx = threadIdx.x, ty = threadIdx.y;   // (32, 8)
#pragma unroll
    for (int i = 0; i < 4; i++)
        t[ty + i*8][tx] = f[(size_t)(c0 + ty + i*8) * 65536 + (x0 + tx)];
    __syncthreads();
#pragma unroll
    for (int i = 0; i < 4; i++)
        d_featT[(size_t)(x0 + ty + i*8) * 256 + (c0 + tx)] = t[tx][ty + i*8];
}

// ---------------- weight repack ----------------
__global__ void k_repack(const float* __restrict__ wt1, const float* __restrict__ wt2,
                         const float* __restrict__ wm) {
    const int total = 262144 * 2 + 32768;
    for (int i = blockIdx.x * blockDim.x + threadIdx.x; i < total;
         i += gridDim.x * blockDim.x) {
        if (i < 262144) {
            int ab = i >> 16, r = i & 65535, c = r >> 8, o = r & 255;
            d_wr1[i] = wt1[((c*256 + o)*2 + (ab>>1))*2 + (ab&1)];
        } else if (i < 524288) {
            int j = i - 262144;
            int ab = j >> 16, r = j & 65535, c = r >> 8, o = r & 255;
            d_wr2[j] = wt2[((c*256 + o)*2 + (ab>>1))*2 + (ab&1)];
        } else {
            int j = i - 524288;
            int c = j >> 7, o = j & 127;
            d_wmT[j] = (o < NCLS) ? wm[o*256 + c] : 0.f;
        }
    }
}

// ---------------- roi_align (ratio=2), output (n, c, OS*OS) ----------------
// BOXSRC 0: proposals (kernel arg); 1: d_boxes (device global)
template<int OS, int BOXSRC>
__global__ void k_roi(const float* __restrict__ bx_in, float* __restrict__ out) {
    const float* bx = (BOXSRC == 0) ? bx_in : d_boxes;
    int n = blockIdx.x, pix = blockIdx.y;
    int oy = pix / OS, ox = pix - oy * OS;
    int c = threadIdx.x;
    float x1 = bx[n*4+0]*SCALE, y1 = bx[n*4+1]*SCALE;
    float x2 = bx[n*4+2]*SCALE, y2 = bx[n*4+3]*SCALE;
    float bw = fmaxf(x2-x1, 1.f) * (1.f/OS);
    float bh = fmaxf(y2-y1, 1.f) * (1.f/OS);
    float acc = 0.f;
#pragma unroll
    for (int sa = 0; sa < 2; sa++) {
        float Y = y1 + ((float)(2*oy+sa) + 0.5f) * 0.5f * bh;
        float y0f = floorf(Y);
        float ly = Y - y0f;
        int y0i = (int)fminf(fmaxf(y0f,     0.f), 255.f);
        int y1i = (int)fminf(fmaxf(y0f+1.f, 0.f), 255.f);
        const float* r0 = d_featT + (size_t)y0i * 65536;
        const float* r1 = d_featT + (size_t)y1i * 65536;
#pragma unroll
        for (int sb = 0; sb < 2; sb++) {
            float X = x1 + ((float)(2*ox+sb) + 0.5f) * 0.5f * bw;
            float x0f = floorf(X);
            float lx = X - x0f;
            int x0i = (int)fminf(fmaxf(x0f,     0.f), 255.f);
            int x1i = (int)fminf(fmaxf(x0f+1.f, 0.f), 255.f);
            float v00 = r0[x0i*256 + c], v01 = r0[x1i*256 + c];
            float v10 = r1[x0i*256 + c], v11 = r1[x1i*256 + c];
            acc += v00*(1.f-ly)*(1.f-lx) + v01*(1.f-ly)*lx
                 + v10*ly*(1.f-lx)       + v11*ly*lx;
        }
    }
    out[((size_t)n*256 + c) * (OS*OS) + pix] = acc * 0.25f;
}

// ---------------- generic 128x128x8 SGEMM ----------------
// C[m,j] = sum_k A[k,m] * B[k,j]
// MODE 0: FC+relu  MODE 1: FC linear  MODE 2: deconv2x2(+relu)  MODE 3: mask head
template<int MODE>
__global__ void __launch_bounds__(256)
k_gemm(const float* __restrict__ A, int lda, int Mv,
       const float* __restrict__ B, int Nv, int K,
       const float* __restrict__ bias,
       float* __restrict__ out, int ldo, int PIX, int IW) {
    __shared__ float As[8][128];
    __shared__ float Bs[8][128];
    const int tid = threadIdx.x;
    const int m0 = blockIdx.x * 128, j0 = blockIdx.y * 128;
    if (MODE == 2) A += (size_t)blockIdx.z * (size_t)K * lda;

    size_t aoff[4]; bool aok[4]; int akl[4], aml[4];
    size_t boff[4]; bool bok[4]; int bkl[4], bjl[4];
#pragma unroll
    for (int i = 0; i < 4; i++) {
        int idx = i*256 + tid;
        int ml = idx & 127, kl = idx >> 7;
        akl[i] = kl; aml[i] = ml;
        aok[i] = (m0 + ml) < Mv;
        aoff[i] = (size_t)kl * lda + (m0 + ml);
    }
    const size_t bstep = (MODE <= 1) ? (size_t)1 : (size_t)PIX;
#pragma unroll
    for (int i = 0; i < 4; i++) {
        int idx = i*256 + tid;
        if (MODE <= 1) {
            int kl = idx & 7, jl = idx >> 3;
            bkl[i] = kl; bjl[i] = jl;
            bok[i] = (j0 + jl) < Nv;
            boff[i] = (size_t)(j0 + jl) * K + kl;
        } else {
            int jl = idx & 127, kl = idx >> 7;
            bkl[i] = kl; bjl[i] = jl;
            int gp = j0 + jl;
            bok[i] = gp < Nv;
            int n = bok[i] ? gp / PIX : 0;
            int p = (bok[i] ? gp : 0) - n * PIX;
            boff[i] = ((size_t)n * K + kl) * (size_t)PIX + p;
        }
    }

    float acc[8][8];
#pragma unroll
    for (int i = 0; i < 8; i++)
#pragma unroll
        for (int j = 0; j < 8; j++) acc[i][j] = 0.f;

    const int ty = tid >> 4, tx = tid & 15;
    for (int k0 = 0; k0 < K; k0 += 8) {
#pragma unroll
        for (int i = 0; i < 4; i++)
            As[akl[i]][aml[i]] = aok[i] ? A[aoff[i] + (size_t)k0 * lda] : 0.f;
#pragma unroll
        for (int i = 0; i < 4; i++)
            Bs[bkl[i]][bjl[i]] = bok[i] ? B[boff[i] + (size_t)k0 * bstep] : 0.f;
        __syncthreads();
#pragma unroll
        for (int kk = 0; kk < 8; kk++) {
            float ra[8], rb[8];
#pragma unroll
            for (int i = 0; i < 8; i++) ra[i] = As[kk][ty*8 + i];
#pragma unroll
            for (int j = 0; j < 8; j++) rb[j] = Bs[kk][tx*8 + j];
#pragma unroll
            for (int i = 0; i < 8; i++)
#pragma unroll
                for (int j = 0; j < 8; j++)
                    acc[i][j] = fmaf(ra[i], rb[j], acc[i][j]);
        }
        __syncthreads();
    }

    if (MODE <= 1) {
#pragma unroll
        for (int j = 0; j < 8; j++) {
            int row = j0 + tx*8 + j;
            if (row >= Nv) continue;
#pragma unroll
            for (int i = 0; i < 8; i++) {
                int col = m0 + ty*8 + i;
                if (col < Mv) {
                    float v = acc[i][j] + bias[col];
                    if (MODE == 0) v = fmaxf(v, 0.f);
                    out[(size_t)row * ldo + col] = v;
                }
            }
        }
    } else if (MODE == 2) {
        int a = blockIdx.z >> 1, b = blockIdx.z & 1;
        int IH = PIX / IW;
#pragma unroll
        for (int j = 0; j < 8; j++) {
            int gp = j0 + tx*8 + j;
            if (gp >= Nv) continue;
            int n = gp / PIX, p = gp - n * PIX;
            int h = p / IW, w = p - h * IW;
#pragma unroll
            for (int i = 0; i < 8; i++) {
                int o = m0 + ty*8 + i;
                size_t oidx = (((size_t)(n*256 + o) * (2*IH) + (2*h + a))
                               * (size_t)(2*IW)) + (2*w + b);
                out[oidx] = fmaxf(acc[i][j] + bias[o], 0.f);
            }
        }
    } else {
#pragma unroll
        for (int j = 0; j < 8; j++) {
            int gp = j0 + tx*8 + j;
            if (gp >= Nv) continue;
            int n = gp / PIX, p = gp - n * PIX;
            float kfn = d_keepf[n];
#pragma unroll
            for (int i = 0; i < 8; i++) {
                int o = m0 + ty*8 + i;
                if (o < Mv)
                    out[((size_t)n * NCLS + o) * (size_t)PIX + p] =
                        (acc[i][j] + bias[o]) * kfn;
            }
        }
    }
}

// ---------------- softmax + argmax + apply_deltas + clip ----------------
__global__ void k_head(const float* __restrict__ props) {
    int i = threadIdx.x;
    if (i >= NP) return;
    const float* lg = d_logit + i * NCLS;
    float mx = -1e30f;
    for (int j = 0; j < NCLS; j++) mx = fmaxf(mx, lg[j]);
    float s = 0.f;
    for (int j = 0; j < NCLS; j++) s += expf(lg[j] - mx);
    float inv = 1.f / s;
    float bmv = -1.f; int bc = 0;
    for (int j = 0; j < NCLS; j++) {
        float p = expf(lg[j] - mx) * inv;
        d_score[i*NCLS + j] = p;
        if (p > bmv) { bmv = p; bc = j; }
    }
    d_bests[i] = bmv;
    float p0 = props[i*4], p1 = props[i*4+1], p2 = props[i*4+2], p3 = props[i*4+3];
    float w = p2 - p0, h = p3 - p1;
    float cx = p0 + 0.5f*w, cy = p1 + 0.5f*h;
    const float* d = d_delt + i * (NCLS*4) + bc*4;
    float px = d[0]*w + cx, py = d[1]*h + cy;
    float pw = expf(d[2])*w, ph = expf(d[3])*h;
    d_boxes[i*4+0] = fminf(fmaxf(px - 0.5f*pw, 0.f), 1024.f);
    d_boxes[i*4+1] = fminf(fmaxf(py - 0.5f*ph, 0.f), 1024.f);
    d_boxes[i*4+2] = fminf(fmaxf(px + 0.5f*pw, 0.f), 1024.f);
    d_boxes[i*4+3] = fminf(fmaxf(py + 0.5f*ph, 0.f), 1024.f);
}

// ---------------- NMS + boxes/scores output ----------------
__global__ void k_nms(float* __restrict__ out) {
    __shared__ float sb[NP*4];
    __shared__ float sarea[NP];
    __shared__ float ss[NP];
    __shared__ int srank[NP];
    __shared__ int skeep[NP];
    int t = threadIdx.x;
    if (t < NP) ss[t] = d_bests[t];
    __syncthreads();
    if (t < NP) {
        float si = ss[t];
        int r = 0;
        for (int j = 0; j < NP; j++) {
            float sj = ss[j];
            r += (sj > si) || (sj == si && j < t);
        }
        srank[t] = r;
        float b0 = d_boxes[t*4],   b1 = d_boxes[t*4+1];
        float b2 = d_boxes[t*4+2], b3 = d_boxes[t*4+3];
        sb[r*4+0] = b0; sb[r*4+1] = b1; sb[r*4+2] = b2; sb[r*4+3] = b3;
        sarea[r] = fmaxf(b2-b0, 0.f) * fmaxf(b3-b1, 0.f);
    }
    __syncthreads();
    for (int i = 0; i < NP; i++) {
        int sup = 0;
        if (t < i && skeep[t]) {
            float xx1 = fmaxf(sb[i*4+0], sb[t*4+0]);
            float yy1 = fmaxf(sb[i*4+1], sb[t*4+1]);
            float xx2 = fminf(sb[i*4+2], sb[t*4+2]);
            float yy2 = fminf(sb[i*4+3], sb[t*4+3]);
            float inter = fmaxf(xx2-xx1, 0.f) * fmaxf(yy2-yy1, 0.f);
            float iou = inter / (sarea[i] + sarea[t] - inter + 1e-9f);
            sup = iou > 0.5f;
        }
        int any = __syncthreads_or(sup);
        if (t == 0) skeep[i] = !any;
        __syncthreads();
    }
    if (t < NP) {
        float kfi = skeep[srank[t]] ? 1.f : 0.f;
        d_keepf[t] = kfi;
        out[t*4+0] = d_boxes[t*4+0]*kfi;
        out[t*4+1] = d_boxes[t*4+1]*kfi;
        out[t*4+2] = d_boxes[t*4+2]*kfi;
        out[t*4+3] = d_boxes[t*4+3]*kfi;
        for (int j = 0; j < NCLS; j++)
            out[NP*4 + t*NCLS + j] = d_score[t*NCLS + j]*kfi;
    }
}

// ---------------- launch ----------------
extern "C" void kernel_launch(void* const* d_in, const int* in_sizes, int n_in,
                              void* d_out, int out_size) {
    const float* feature = (const float*)d_in[0];
    const float* props   = (const float*)d_in[1];
    const float* w1      = (const float*)d_in[2];
    const float* b1      = (const float*)d_in[3];
    const float* w2      = (const float*)d_in[4];
    const float* b2      = (const float*)d_in[5];
    const float* w_box   = (const float*)d_in[6];
    const float* b_box   = (const float*)d_in[7];
    const float* w_cls   = (const float*)d_in[8];
    const float* b_cls   = (const float*)d_in[9];
    const float* wt1     = (const float*)d_in[10];
    const float* bt1     = (const float*)d_in[11];
    const float* wt2     = (const float*)d_in[12];
    const float* bt2     = (const float*)d_in[13];
    const float* wm      = (const float*)d_in[14];
    const float* bm      = (const float*)d_in[15];
    float* out = (float*)d_out;

    static float *roi7 = nullptr, *h1, *h2, *delt, *logit;
    static float *roi14, *m1, *m2, *wr1, *wr2, *wmT;
    if (!roi7) {   // one-time, allocation-free symbol resolution
        cudaGetSymbolAddress((void**)&roi7,  d_roi7);
        cudaGetSymbolAddress((void**)&h1,    d_h1);
        cudaGetSymbolAddress((void**)&h2,    d_h2);
        cudaGetSymbolAddress((void**)&delt,  d_delt);
        cudaGetSymbolAddress((void**)&logit, d_logit);
        cudaGetSymbolAddress((void**)&roi14, d_roi14);
        cudaGetSymbolAddress((void**)&m1,    d_m1);
        cudaGetSymbolAddress((void**)&m2,    d_m2);
        cudaGetSymbolAddress((void**)&wr1,   d_wr1);
        cudaGetSymbolAddress((void**)&wr2,   d_wr2);
        cudaGetSymbolAddress((void**)&wmT,   d_wmT);
    }

    k_transpose<<<dim3(2048, 8), dim3(32, 8)>>>(feature);
    k_repack<<<1088, 256>>>(wt1, wt2, wm);
    k_roi<7, 0><<<dim3(NP, 49), 256>>>(props, roi7);

    // FC1: M(cols)=1024, N(rows)=200, K=12544
    k_gemm<0><<<dim3(8, 2, 1), 256>>>(w1, 1024, 1024, roi7, NP, 12544,
                                      b1, h1, 1024, 1, 1);
    k_gemm<0><<<dim3(8, 2, 1), 256>>>(w2, 1024, 1024, h1, NP, 1024,
                                      b2, h2, 1024, 1, 1);
    k_gemm<1><<<dim3(3, 2, 1), 256>>>(w_box, NCLS*4, NCLS*4, h2, NP, 1024,
                                      b_box, delt, NCLS*4, 1, 1);
    k_gemm<1><<<dim3(1, 2, 1), 256>>>(w_cls, NCLS, NCLS, h2, NP, 1024,
                                      b_cls, logit, NCLS, 1, 1);

    k_head<<<1, 256>>>(props);
    k_nms<<<1, 256>>>(out);

    k_roi<14, 1><<<dim3(NP, 196), 256>>>(nullptr, roi14);

    // deconv1: M=256(o), N=200*196 px, K=256, z=(a,b)
    k_gemm<2><<<dim3(2, 307, 4), 256>>>(wr1, 256, 256, roi14, NP*196, 256,
                                        bt1, m1, 0, 196, 14);
    // deconv2: N=200*784
    k_gemm<2><<<dim3(2, 1225, 4), 256>>>(wr2, 256, 256, m1, NP*784, 256,
                                         bt2, m2, 0, 784, 28);
    // mask head: M=81(pad128), N=200*3136, K=256
    k_gemm<3><<<dim3(1, 4900, 1), 256>>>(wmT, 128, NCLS, m2, NP*3136, 256,
                                         bm, out + NP*4 + NP*NCLS, 0, 3136, 56);
}

// round 4
// speedup vs baseline: 1.8276x; 1.8276x over previous
#include <cuda_runtime.h>
#include <math.h>

#define NP 200
#define NCLS 81
#define SCALE (1.0f/16.0f)

// ---------------- scratch (static device arrays; no allocations) ----------------
__device__ float d_featT[(size_t)256*256*256];          // 64 MB  (HWC)
__device__ float d_roi7 [(size_t)NP*256*49];            // 10 MB  (n,c,p)
__device__ float d_part [16*NP*1024];                   // split-K partials
__device__ float d_h1   [NP*1024];
__device__ float d_h2   [NP*1024];
__device__ float d_delt [NP*NCLS*4];
__device__ float d_logit[NP*NCLS];
__device__ float d_score[NP*NCLS];
__device__ float d_bests[NP];
__device__ float d_boxes[NP*4];
__device__ float d_keepf[NP];
__device__ float d_roi14[(size_t)NP*256*196];           // 40 MB
__device__ float d_m1   [(size_t)NP*256*784];           // 160 MB (n,c,28,28)
__device__ float d_m2   [(size_t)NP*256*3136];          // 642 MB (n,c,56,56)
__device__ float d_wr1  [4*256*256];                    // [ab][c][o]
__device__ float d_wr2  [4*256*256];
__device__ float d_wmT  [256*128];                      // [c][o] padded to 128

// ---------------- feature transpose: (C,H,W) -> (H*W, C) ----------------
__global__ void k_transpose(const float* __restrict__ f) {
    __shared__ float t[32][33];
    int x0 = blockIdx.x * 32, c0 = blockIdx.y * 32;
    int tx = threadIdx.x, ty = threadIdx.y;   // (32, 8)
#pragma unroll
    for (int i = 0; i < 4; i++)
        t[ty + i*8][tx] = f[(size_t)(c0 + ty + i*8) * 65536 + (x0 + tx)];
    __syncthreads();
#pragma unroll
    for (int i = 0; i < 4; i++)
        d_featT[(size_t)(x0 + ty + i*8) * 256 + (c0 + tx)] = t[tx][ty + i*8];
}

// ---------------- weight repack ----------------
__global__ void k_repack(const float* __restrict__ wt1, const float* __restrict__ wt2,
                         const float* __restrict__ wm) {
    const int total = 262144 * 2 + 32768;
    for (int i = blockIdx.x * blockDim.x + threadIdx.x; i < total;
         i += gridDim.x * blockDim.x) {
        if (i < 262144) {
            int ab = i >> 16, r = i & 65535, c = r >> 8, o = r & 255;
            d_wr1[i] = wt1[((c*256 + o)*2 + (ab>>1))*2 + (ab&1)];
        } else if (i < 524288) {
            int j = i - 262144;
            int ab = j >> 16, r = j & 65535, c = r >> 8, o = r & 255;
            d_wr2[j] = wt2[((c*256 + o)*2 + (ab>>1))*2 + (ab&1)];
        } else {
            int j = i - 524288;
            int c = j >> 7, o = j & 127;
            d_wmT[j] = (o < NCLS) ? wm[o*256 + c] : 0.f;
        }
    }
}

// ---------------- roi_align (ratio=2), output (n, c, OS*OS) ----------------
// BOXSRC 0: proposals (kernel arg); 1: d_boxes + skip dropped n
template<int OS, int BOXSRC>
__global__ void k_roi(const float* __restrict__ bx_in, float* __restrict__ out) {
    const float* bx = (BOXSRC == 0) ? bx_in : d_boxes;
    int n = blockIdx.x, pix = blockIdx.y;
    if (BOXSRC == 1 && d_keepf[n] == 0.f) return;
    int oy = pix / OS, ox = pix - oy * OS;
    int c = threadIdx.x;
    float x1 = bx[n*4+0]*SCALE, y1 = bx[n*4+1]*SCALE;
    float x2 = bx[n*4+2]*SCALE, y2 = bx[n*4+3]*SCALE;
    float bw = fmaxf(x2-x1, 1.f) * (1.f/OS);
    float bh = fmaxf(y2-y1, 1.f) * (1.f/OS);
    float acc = 0.f;
#pragma unroll
    for (int sa = 0; sa < 2; sa++) {
        float Y = y1 + ((float)(2*oy+sa) + 0.5f) * 0.5f * bh;
        float y0f = floorf(Y);
        float ly = Y - y0f;
        int y0i = (int)fminf(fmaxf(y0f,     0.f), 255.f);
        int y1i = (int)fminf(fmaxf(y0f+1.f, 0.f), 255.f);
        const float* r0 = d_featT + (size_t)y0i * 65536;
        const float* r1 = d_featT + (size_t)y1i * 65536;
#pragma unroll
        for (int sb = 0; sb < 2; sb++) {
            float X = x1 + ((float)(2*ox+sb) + 0.5f) * 0.5f * bw;
            float x0f = floorf(X);
            float lx = X - x0f;
            int x0i = (int)fminf(fmaxf(x0f,     0.f), 255.f);
            int x1i = (int)fminf(fmaxf(x0f+1.f, 0.f), 255.f);
            float v00 = r0[x0i*256 + c], v01 = r0[x1i*256 + c];
            float v10 = r1[x0i*256 + c], v11 = r1[x1i*256 + c];
            acc += v00*(1.f-ly)*(1.f-lx) + v01*(1.f-ly)*lx
                 + v10*ly*(1.f-lx)       + v11*ly*lx;
        }
    }
    out[((size_t)n*256 + c) * (OS*OS) + pix] = acc * 0.25f;
}

// ---------------- split-K FC GEMM ----------------
// part[(z*NP + row)*ldo + col] = sum_{k in split z} A[k][col] * B[row][k]
__global__ void __launch_bounds__(256)
k_skgemm(const float* __restrict__ A, int lda, int Mv,
         const float* __restrict__ B, int Kfull, int Ksplit,
         float* __restrict__ out, int ldo) {
    __shared__ float As[8][128];
    __shared__ float Bs[8][128];
    const int tid = threadIdx.x;
    const int m0 = blockIdx.x * 128, j0 = blockIdx.y * 128;
    const int z  = blockIdx.z;
    A += (size_t)z * Ksplit * lda;
    const int kbase = z * Ksplit;

    int akl[4], aml[4]; bool aok[4];
    int bkl[4], bjl[4]; bool bok[4];
#pragma unroll
    for (int i = 0; i < 4; i++) {
        int idx = i*256 + tid;
        aml[i] = idx & 127; akl[i] = idx >> 7;
        aok[i] = (m0 + aml[i]) < Mv;
        bkl[i] = idx & 7; bjl[i] = idx >> 3;
        bok[i] = (j0 + bjl[i]) < NP;
    }

    float acc[8][8];
#pragma unroll
    for (int i = 0; i < 8; i++)
#pragma unroll
        for (int j = 0; j < 8; j++) acc[i][j] = 0.f;

    const int ty = tid >> 4, tx = tid & 15;
    for (int k0 = 0; k0 < Ksplit; k0 += 8) {
#pragma unroll
        for (int i = 0; i < 4; i++)
            As[akl[i]][aml[i]] = aok[i] ? A[(size_t)(k0 + akl[i]) * lda + m0 + aml[i]] : 0.f;
#pragma unroll
        for (int i = 0; i < 4; i++)
            Bs[bkl[i]][bjl[i]] = bok[i]
                ? B[(size_t)(j0 + bjl[i]) * Kfull + kbase + k0 + bkl[i]] : 0.f;
        __syncthreads();
#pragma unroll
        for (int kk = 0; kk < 8; kk++) {
            float ra[8], rb[8];
#pragma unroll
            for (int i = 0; i < 8; i++) ra[i] = As[kk][ty*8 + i];
#pragma unroll
            for (int j = 0; j < 8; j++) rb[j] = Bs[kk][tx*8 + j];
#pragma unroll
            for (int i = 0; i < 8; i++)
#pragma unroll
                for (int j = 0; j < 8; j++)
                    acc[i][j] = fmaf(ra[i], rb[j], acc[i][j]);
        }
        __syncthreads();
    }
#pragma unroll
    for (int j = 0; j < 8; j++) {
        int row = j0 + tx*8 + j;
        if (row >= NP) continue;
#pragma unroll
        for (int i = 0; i < 8; i++) {
            int col = m0 + ty*8 + i;
            if (col < Mv)
                out[((size_t)z * NP + row) * ldo + col] = acc[i][j];
        }
    }
}

// reduce split-K partials + bias (+relu)
__global__ void k_reduce(const float* __restrict__ part, const float* __restrict__ bias,
                         float* __restrict__ out, int nelem, int ld, int nsplit, int relu) {
    int i = blockIdx.x * blockDim.x + threadIdx.x;
    if (i >= nelem) return;
    int col = i % ld;
    float s = 0.f;
    for (int zz = 0; zz < nsplit; zz++) s += part[(size_t)zz * nelem + i];
    s += bias[col];
    if (relu) s = fmaxf(s, 0.f);
    out[i] = s;
}

// ---------------- pixel GEMM: double-buffered 128x128, K=256 fixed ----------------
// MODE 2: deconv2x2 (+relu). blockIdx.z = n*4 + ab. A = wr [ab][256 k][256 o].
// MODE 3: mask head. blockIdx.z = n. A = wmT [256 k][128 o]. zero-fill if dropped.
template<int MODE, int PIX, int IW>
__global__ void __launch_bounds__(256, 2)
k_pgemm(const float* __restrict__ A, const float* __restrict__ Bsrc,
        const float* __restrict__ bias, float* __restrict__ out) {
    constexpr int K = 256;
    constexpr int LDA = (MODE == 2) ? 256 : 128;
    constexpr int IH = PIX / IW;
    __shared__ float As[2][8][128];
    __shared__ float Bs[2][8][128];
    const int tid = threadIdx.x;
    const int mtile = blockIdx.x;
    const int p0 = blockIdx.y * 128;
    const int nz = blockIdx.z;
    const int n  = (MODE == 2) ? (nz >> 2) : nz;
    const int ab = (MODE == 2) ? (nz & 3) : 0;
    const int ty = tid >> 4, tx = tid & 15;
    const float kfn = d_keepf[n];

    if (MODE == 3 && kfn == 0.f) {     // output must be fully written (poisoned)
#pragma unroll
        for (int j = 0; j < 8; j++) {
            int p = p0 + tx*8 + j;
            if (p >= PIX) continue;
#pragma unroll
            for (int i = 0; i < 8; i++) {
                int o = ty*8 + i;
                if (o < NCLS)
                    out[((size_t)n * NCLS + o) * PIX + p] = 0.f;
            }
        }
        return;
    }
    if (MODE == 2 && kfn == 0.f) return;

    const float* Ap = A + ((MODE == 2) ? (size_t)ab * K * LDA : (size_t)0) + mtile * 128;
    const float* Bp = Bsrc + (size_t)n * K * PIX + p0;

    const int lkl = tid >> 5;          // 0..7
    const int lmv = (tid & 31) * 4;    // 0..124
    const bool bok = (p0 + lmv) < PIX; // PIX%4==0, lmv 4-aligned -> vector-safe

    float4 rA = *(const float4*)(Ap + (size_t)lkl * LDA + lmv);
    float4 rB = bok ? *(const float4*)(Bp + (size_t)lkl * PIX + lmv)
                    : make_float4(0.f, 0.f, 0.f, 0.f);
    *(float4*)&As[0][lkl][lmv] = rA;
    *(float4*)&Bs[0][lkl][lmv] = rB;
    __syncthreads();

    float acc[8][8];
#pragma unroll
    for (int i = 0; i < 8; i++)
#pragma unroll
        for (int j = 0; j < 8; j++) acc[i][j] = 0.f;

#pragma unroll 1
    for (int kt = 0; kt < K/8; kt++) {
        const int cur = kt & 1;
        if (kt < K/8 - 1) {
            const int k1 = (kt + 1) * 8;
            rA = *(const float4*)(Ap + (size_t)(k1 + lkl) * LDA + lmv);
            rB = bok ? *(const float4*)(Bp + (size_t)(k1 + lkl) * PIX + lmv)
                     : make_float4(0.f, 0.f, 0.f, 0.f);
        }
        const float (*Ac)[128] = As[cur];
        const float (*Bc)[128] = Bs[cur];
#pragma unroll
        for (int kk = 0; kk < 8; kk++) {
            float ra[8], rb[8];
#pragma unroll
            for (int i = 0; i < 8; i++) ra[i] = Ac[kk][ty*8 + i];
#pragma unroll
            for (int j = 0; j < 8; j++) rb[j] = Bc[kk][tx*8 + j];
#pragma unroll
            for (int i = 0; i < 8; i++)
#pragma unroll
                for (int j = 0; j < 8; j++)
                    acc[i][j] = fmaf(ra[i], rb[j], acc[i][j]);
        }
        if (kt < K/8 - 1) {
            const int nxt = cur ^ 1;
            *(float4*)&As[nxt][lkl][lmv] = rA;
            *(float4*)&Bs[nxt][lkl][lmv] = rB;
        }
        __syncthreads();
    }

    if (MODE == 2) {
        const int a = ab >> 1, b = ab & 1;
#pragma unroll
        for (int j = 0; j < 8; j++) {
            int p = p0 + tx*8 + j;
            if (p >= PIX) continue;
            int h = p / IW, w = p - h * IW;
#pragma unroll
            for (int i = 0; i < 8; i++) {
                int o = mtile * 128 + ty*8 + i;
                size_t oidx = (((size_t)(n*256 + o) * (2*IH) + (2*h + a))
                               * (size_t)(2*IW)) + (2*w + b);
                out[oidx] = fmaxf(acc[i][j] + bias[o], 0.f);
            }
        }
    } else {
#pragma unroll
        for (int j = 0; j < 8; j++) {
            int p = p0 + tx*8 + j;
            if (p >= PIX) continue;
#pragma unroll
            for (int i = 0; i < 8; i++) {
                int o = ty*8 + i;
                if (o < NCLS)
                    out[((size_t)n * NCLS + o) * PIX + p] = acc[i][j] + bias[o];
            }
        }
    }
}

// ---------------- softmax + argmax + apply_deltas + clip ----------------
__global__ void k_head(const float* __restrict__ props) {
    int i = threadIdx.x;
    if (i >= NP) return;
    const float* lg = d_logit + i * NCLS;
    float mx = -1e30f;
    for (int j = 0; j < NCLS; j++) mx = fmaxf(mx, lg[j]);
    float s = 0.f;
    for (int j = 0; j < NCLS; j++) s += expf(lg[j] - mx);
    float inv = 1.f / s;
    float bmv = -1.f; int bc = 0;
    for (int j = 0; j < NCLS; j++) {
        float p = expf(lg[j] - mx) * inv;
        d_score[i*NCLS + j] = p;
        if (p > bmv) { bmv = p; bc = j; }
    }
    d_bests[i] = bmv;
    float p0 = props[i*4], p1 = props[i*4+1], p2 = props[i*4+2], p3 = props[i*4+3];
    float w = p2 - p0, h = p3 - p1;
    float cx = p0 + 0.5f*w, cy = p1 + 0.5f*h;
    const float* d = d_delt + i * (NCLS*4) + bc*4;
    float px = d[0]*w + cx, py = d[1]*h + cy;
    float pw = expf(d[2])*w, ph = expf(d[3])*h;
    d_boxes[i*4+0] = fminf(fmaxf(px - 0.5f*pw, 0.f), 1024.f);
    d_boxes[i*4+1] = fminf(fmaxf(py - 0.5f*ph, 0.f), 1024.f);
    d_boxes[i*4+2] = fminf(fmaxf(px + 0.5f*pw, 0.f), 1024.f);
    d_boxes[i*4+3] = fminf(fmaxf(py + 0.5f*ph, 0.f), 1024.f);
}

// ---------------- NMS + boxes/scores output ----------------
__global__ void k_nms(float* __restrict__ out) {
    __shared__ float sb[NP*4];
    __shared__ float sarea[NP];
    __shared__ float ss[NP];
    __shared__ int srank[NP];
    __shared__ int skeep[NP];
    int t = threadIdx.x;
    if (t < NP) ss[t] = d_bests[t];
    __syncthreads();
    if (t < NP) {
        float si = ss[t];
        int r = 0;
        for (int j = 0; j < NP; j++) {
            float sj = ss[j];
            r += (sj > si) || (sj == si && j < t);
        }
        srank[t] = r;
        float b0 = d_boxes[t*4],   b1 = d_boxes[t*4+1];
        float b2 = d_boxes[t*4+2], b3 = d_boxes[t*4+3];
        sb[r*4+0] = b0; sb[r*4+1] = b1; sb[r*4+2] = b2; sb[r*4+3] = b3;
        sarea[r] = fmaxf(b2-b0, 0.f) * fmaxf(b3-b1, 0.f);
    }
    __syncthreads();
    for (int i = 0; i < NP; i++) {
        int sup = 0;
        if (t < i && skeep[t]) {
            float xx1 = fmaxf(sb[i*4+0], sb[t*4+0]);
            float yy1 = fmaxf(sb[i*4+1], sb[t*4+1]);
            float xx2 = fminf(sb[i*4+2], sb[t*4+2]);
            float yy2 = fminf(sb[i*4+3], sb[t*4+3]);
            float inter = fmaxf(xx2-xx1, 0.f) * fmaxf(yy2-yy1, 0.f);
            float iou = inter / (sarea[i] + sarea[t] - inter + 1e-9f);
            sup = iou > 0.5f;
        }
        int any = __syncthreads_or(sup);
        if (t == 0) skeep[i] = !any;
        __syncthreads();
    }
    if (t < NP) {
        float kfi = skeep[srank[t]] ? 1.f : 0.f;
        d_keepf[t] = kfi;
        out[t*4+0] = d_boxes[t*4+0]*kfi;
        out[t*4+1] = d_boxes[t*4+1]*kfi;
        out[t*4+2] = d_boxes[t*4+2]*kfi;
        out[t*4+3] = d_boxes[t*4+3]*kfi;
        for (int j = 0; j < NCLS; j++)
            out[NP*4 + t*NCLS + j] = d_score[t*NCLS + j]*kfi;
    }
}

// ---------------- launch ----------------
extern "C" void kernel_launch(void* const* d_in, const int* in_sizes, int n_in,
                              void* d_out, int out_size) {
    const float* feature = (const float*)d_in[0];
    const float* props   = (const float*)d_in[1];
    const float* w1      = (const float*)d_in[2];
    const float* b1      = (const float*)d_in[3];
    const float* w2      = (const float*)d_in[4];
    const float* b2      = (const float*)d_in[5];
    const float* w_box   = (const float*)d_in[6];
    const float* b_box   = (const float*)d_in[7];
    const float* w_cls   = (const float*)d_in[8];
    const float* b_cls   = (const float*)d_in[9];
    const float* wt1     = (const float*)d_in[10];
    const float* bt1     = (const float*)d_in[11];
    const float* wt2     = (const float*)d_in[12];
    const float* bt2     = (const float*)d_in[13];
    const float* wm      = (const float*)d_in[14];
    const float* bm      = (const float*)d_in[15];
    float* out = (float*)d_out;

    static float *roi7 = nullptr, *part, *h1, *h2, *delt, *logit;
    static float *roi14, *m1, *m2, *wr1, *wr2, *wmT;
    if (!roi7) {   // one-time, allocation-free symbol resolution
        cudaGetSymbolAddress((void**)&roi7,  d_roi7);
        cudaGetSymbolAddress((void**)&part,  d_part);
        cudaGetSymbolAddress((void**)&h1,    d_h1);
        cudaGetSymbolAddress((void**)&h2,    d_h2);
        cudaGetSymbolAddress((void**)&delt,  d_delt);
        cudaGetSymbolAddress((void**)&logit, d_logit);
        cudaGetSymbolAddress((void**)&roi14, d_roi14);
        cudaGetSymbolAddress((void**)&m1,    d_m1);
        cudaGetSymbolAddress((void**)&m2,    d_m2);
        cudaGetSymbolAddress((void**)&wr1,   d_wr1);
        cudaGetSymbolAddress((void**)&wr2,   d_wr2);
        cudaGetSymbolAddress((void**)&wmT,   d_wmT);
    }

    k_transpose<<<dim3(2048, 8), dim3(32, 8)>>>(feature);
    k_repack<<<1088, 256>>>(wt1, wt2, wm);
    k_roi<7, 0><<<dim3(NP, 49), 256>>>(props, roi7);

    // FC1: 1024 cols, 200 rows, K=12544, split-K 16 x 784
    k_skgemm<<<dim3(8, 2, 16), 256>>>(w1, 1024, 1024, roi7, 12544, 784, part, 1024);
    k_reduce<<<800, 256>>>(part, b1, h1, NP*1024, 1024, 16, 1);
    // FC2: K=1024, split 8 x 128
    k_skgemm<<<dim3(8, 2, 8), 256>>>(w2, 1024, 1024, h1, 1024, 128, part, 1024);
    k_reduce<<<800, 256>>>(part, b2, h2, NP*1024, 1024, 8, 1);
    // box head
    k_skgemm<<<dim3(3, 2, 8), 256>>>(w_box, NCLS*4, NCLS*4, h2, 1024, 128, part, NCLS*4);
    k_reduce<<<(NP*NCLS*4 + 255)/256, 256>>>(part, b_box, delt, NP*NCLS*4, NCLS*4, 8, 0);
    // cls head
    k_skgemm<<<dim3(1, 2, 8), 256>>>(w_cls, NCLS, NCLS, h2, 1024, 128, part, NCLS);
    k_reduce<<<(NP*NCLS + 255)/256, 256>>>(part, b_cls, logit, NP*NCLS, NCLS, 8, 0);

    k_head<<<1, 256>>>(props);
    k_nms<<<1, 256>>>(out);

    k_roi<14, 1><<<dim3(NP, 196), 256>>>(nullptr, roi14);

    // deconv1: per-n tiles, z = n*4 + ab
    k_pgemm<2, 196, 14><<<dim3(2, 2, NP*4), 256>>>(wr1, roi14, bt1, m1);
    // deconv2
    k_pgemm<2, 784, 28><<<dim3(2, 7, NP*4), 256>>>(wr2, m1, bt2, m2);
    // mask head (writes/zero-fills every mask output element)
    k_pgemm<3, 3136, 56><<<dim3(1, 25, NP), 256>>>(wmT, m2, bm, out + NP*4 + NP*NCLS);
}

// round 6
// speedup vs baseline: 1.9832x; 1.0851x over previous
#include <cuda_runtime.h>
#include <math.h>
#include <stdint.h>

#define NP 200
#define NCLS 81
#define SCALE (1.0f/16.0f)

typedef unsigned long long u64;

// ---------------- packed f32x2 helpers (Blackwell base-family ISA) ----------------
__device__ __forceinline__ u64 pack2_dup(float a) {
    u64 r; asm("mov.b64 %0, {%1, %1};" : "=l"(r) : "f"(a)); return r;
}
__device__ __forceinline__ void fma2(u64& acc, u64 a, u64 b) {
    asm("fma.rn.f32x2 %0, %1, %2, %0;" : "+l"(acc) : "l"(a), "l"(b));
}
__device__ __forceinline__ float2 unpack2(u64 v) {
    float2 f; asm("mov.b64 {%0, %1}, %2;" : "=f"(f.x), "=f"(f.y) : "l"(v)); return f;
}

// ---------------- scratch (static device arrays; no allocations) ----------------
__device__ float d_featT[(size_t)256*256*256];          // 64 MB  (HWC)
__device__ float d_roi7 [(size_t)NP*256*49];            // 10 MB  (n,c,p)
__device__ float d_part [16*NP*1024];                   // split-K partials
__device__ float d_h1   [NP*1024];
__device__ float d_h2   [NP*1024];
__device__ float d_delt [NP*NCLS*4];
__device__ float d_logit[NP*NCLS];
__device__ float d_score[NP*NCLS];
__device__ float d_bests[NP];
__device__ float d_boxes[NP*4];
__device__ float d_keepf[NP];
__device__ float d_roi14[(size_t)NP*256*196];           // 40 MB
__device__ float d_m1   [(size_t)NP*256*784];           // 160 MB (n,c,28,28)
__device__ float d_m2   [(size_t)NP*256*3136];          // 642 MB (n,c,56,56)
__device__ float d_wr1  [4*256*256];                    // [ab][c][o]
__device__ float d_wr2  [4*256*256];
__device__ float d_wmT  [256*128];                      // [c][o] padded to 128

// ---------------- feature transpose: (C,H,W) -> (H*W, C) ----------------
__global__ void k_transpose(const float* __restrict__ f) {
    __shared__ float t[32][33];
    int x0 = blockIdx.x * 32, c0 = blockIdx.y * 32;
    int tx = threadIdx.x, ty = threadIdx.y;   // (32, 8)
#pragma unroll
    for (int i = 0; i < 4; i++)
        t[ty + i*8][tx] = f[(size_t)(c0 + ty + i*8) * 65536 + (x0 + tx)];
    __syncthreads();
#pragma unroll
    for (int i = 0; i < 4; i++)
        d_featT[(size_t)(x0 + ty + i*8) * 256 + (c0 + tx)] = t[tx][ty + i*8];
}

// ---------------- weight repack ----------------
__global__ void k_repack(const float* __restrict__ wt1, const float* __restrict__ wt2,
                         const float* __restrict__ wm) {
    const int total = 262144 * 2 + 32768;
    for (int i = blockIdx.x * blockDim.x + threadIdx.x; i < total;
         i += gridDim.x * blockDim.x) {
        if (i < 262144) {
            int ab = i >> 16, r = i & 65535, c = r >> 8, o = r & 255;
            d_wr1[i] = wt1[((c*256 + o)*2 + (ab>>1))*2 + (ab&1)];
        } else if (i < 524288) {
            int j = i - 262144;
            int ab = j >> 16, r = j & 65535, c = r >> 8, o = r & 255;
            d_wr2[j] = wt2[((c*256 + o)*2 + (ab>>1))*2 + (ab&1)];
        } else {
            int j = i - 524288;
            int c = j >> 7, o = j & 127;
            d_wmT[j] = (o < NCLS) ? wm[o*256 + c] : 0.f;
        }
    }
}

// ---------------- roi_align (ratio=2), output (n, c, OS*OS) ----------------
// BOXSRC 0: proposals (kernel arg); 1: d_boxes + skip dropped n
template<int OS, int BOXSRC>
__global__ void k_roi(const float* __restrict__ bx_in, float* __restrict__ out) {
    const float* bx = (BOXSRC == 0) ? bx_in : d_boxes;
    int n = blockIdx.x, pix = blockIdx.y;
    if (BOXSRC == 1 && d_keepf[n] == 0.f) return;
    int oy = pix / OS, ox = pix - oy * OS;
    int c = threadIdx.x;
    float x1 = bx[n*4+0]*SCALE, y1 = bx[n*4+1]*SCALE;
    float x2 = bx[n*4+2]*SCALE, y2 = bx[n*4+3]*SCALE;
    float bw = fmaxf(x2-x1, 1.f) * (1.f/OS);
    float bh = fmaxf(y2-y1, 1.f) * (1.f/OS);
    float acc = 0.f;
#pragma unroll
    for (int sa = 0; sa < 2; sa++) {
        float Y = y1 + ((float)(2*oy+sa) + 0.5f) * 0.5f * bh;
        float y0f = floorf(Y);
        float ly = Y - y0f;
        int y0i = (int)fminf(fmaxf(y0f,     0.f), 255.f);
        int y1i = (int)fminf(fmaxf(y0f+1.f, 0.f), 255.f);
        const float* r0 = d_featT + (size_t)y0i * 65536;
        const float* r1 = d_featT + (size_t)y1i * 65536;
#pragma unroll
        for (int sb = 0; sb < 2; sb++) {
            float X = x1 + ((float)(2*ox+sb) + 0.5f) * 0.5f * bw;
            float x0f = floorf(X);
            float lx = X - x0f;
            int x0i = (int)fminf(fmaxf(x0f,     0.f), 255.f);
            int x1i = (int)fminf(fmaxf(x0f+1.f, 0.f), 255.f);
            float v00 = r0[x0i*256 + c], v01 = r0[x1i*256 + c];
            float v10 = r1[x0i*256 + c], v11 = r1[x1i*256 + c];
            acc += v00*(1.f-ly)*(1.f-lx) + v01*(1.f-ly)*lx
                 + v10*ly*(1.f-lx)       + v11*ly*lx;
        }
    }
    out[((size_t)n*256 + c) * (OS*OS) + pix] = acc * 0.25f;
}

// ---------------- split-K FC GEMM (packed f32x2 FMA) ----------------
// part[(z*NP + row)*ldo + col] = sum_{k in split z} A[k][col] * B[row][k]
__global__ void __launch_bounds__(256)
k_skgemm(const float* __restrict__ A, int lda, int Mv,
         const float* __restrict__ B, int Kfull, int Ksplit,
         float* __restrict__ out, int ldo) {
    __shared__ float As[8][128];
    __shared__ float Bs[8][128];
    const int tid = threadIdx.x;
    const int m0 = blockIdx.x * 128, j0 = blockIdx.y * 128;
    const int z  = blockIdx.z;
    A += (size_t)z * Ksplit * lda;
    const int kbase = z * Ksplit;

    int akl[4], aml[4]; bool aok[4];
    int bkl[4], bjl[4]; bool bok[4];
#pragma unroll
    for (int i = 0; i < 4; i++) {
        int idx = i*256 + tid;
        aml[i] = idx & 127; akl[i] = idx >> 7;
        aok[i] = (m0 + aml[i]) < Mv;
        bkl[i] = idx & 7; bjl[i] = idx >> 3;
        bok[i] = (j0 + bjl[i]) < NP;
    }

    u64 acc2[8][4];
#pragma unroll
    for (int i = 0; i < 8; i++)
#pragma unroll
        for (int j = 0; j < 4; j++) acc2[i][j] = 0ull;

    const int ty = tid >> 4, tx = tid & 15;
    for (int k0 = 0; k0 < Ksplit; k0 += 8) {
#pragma unroll
        for (int i = 0; i < 4; i++)
            As[akl[i]][aml[i]] = aok[i] ? A[(size_t)(k0 + akl[i]) * lda + m0 + aml[i]] : 0.f;
#pragma unroll
        for (int i = 0; i < 4; i++)
            Bs[bkl[i]][bjl[i]] = bok[i]
                ? B[(size_t)(j0 + bjl[i]) * Kfull + kbase + k0 + bkl[i]] : 0.f;
        __syncthreads();
#pragma unroll
        for (int kk = 0; kk < 8; kk++) {
            u64 ra2[8], rb2[4];
#pragma unroll
            for (int i = 0; i < 8; i++) ra2[i] = pack2_dup(As[kk][ty*8 + i]);
#pragma unroll
            for (int j = 0; j < 4; j++) rb2[j] = *(const u64*)&Bs[kk][tx*8 + 2*j];
#pragma unroll
            for (int i = 0; i < 8; i++)
#pragma unroll
                for (int j = 0; j < 4; j++)
                    fma2(acc2[i][j], ra2[i], rb2[j]);
        }
        __syncthreads();
    }
#pragma unroll
    for (int j4 = 0; j4 < 4; j4++) {
#pragma unroll
        for (int jj = 0; jj < 2; jj++) {
            int row = j0 + tx*8 + 2*j4 + jj;
            if (row >= NP) continue;
#pragma unroll
            for (int i = 0; i < 8; i++) {
                int col = m0 + ty*8 + i;
                if (col < Mv) {
                    float2 v = unpack2(acc2[i][j4]);
                    out[((size_t)z * NP + row) * ldo + col] = jj ? v.y : v.x;
                }
            }
        }
    }
}

// reduce split-K partials + bias (+relu)
__global__ void k_reduce(const float* __restrict__ part, const float* __restrict__ bias,
                         float* __restrict__ out, int nelem, int ld, int nsplit, int relu) {
    int i = blockIdx.x * blockDim.x + threadIdx.x;
    if (i >= nelem) return;
    int col = i % ld;
    float s = 0.f;
    for (int zz = 0; zz < nsplit; zz++) s += part[(size_t)zz * nelem + i];
    s += bias[col];
    if (relu) s = fmaxf(s, 0.f);
    out[i] = s;
}

// ---------------- pixel GEMM: double-buffered 128x128, K=256, packed f32x2 ----------------
// MODE 2: deconv2x2 (+relu). blockIdx.z = n*4 + ab. A = wr [ab][256 k][256 o].
// MODE 3: mask head. blockIdx.z = n. A = wmT [256 k][128 o]. zero-fill if dropped.
template<int MODE, int PIX, int IW>
__global__ void __launch_bounds__(256, 2)
k_pgemm(const float* __restrict__ A, const float* __restrict__ Bsrc,
        const float* __restrict__ bias, float* __restrict__ out) {
    constexpr int K = 256;
    constexpr int LDA = (MODE == 2) ? 256 : 128;
    constexpr int IH = PIX / IW;
    __shared__ float As[2][8][128];
    __shared__ float Bs[2][8][128];
    const int tid = threadIdx.x;
    const int mtile = blockIdx.x;
    const int p0 = blockIdx.y * 128;
    const int nz = blockIdx.z;
    const int n  = (MODE == 2) ? (nz >> 2) : nz;
    const int ab = (MODE == 2) ? (nz & 3) : 0;
    const int ty = tid >> 4, tx = tid & 15;
    const float kfn = d_keepf[n];

    if (MODE == 3 && kfn == 0.f) {     // output must be fully written (poisoned)
#pragma unroll
        for (int j = 0; j < 8; j++) {
            int p = p0 + tx*8 + j;
            if (p >= PIX) continue;
#pragma unroll
            for (int i = 0; i < 8; i++) {
                int o = ty*8 + i;
                if (o < NCLS)
                    out[((size_t)n * NCLS + o) * PIX + p] = 0.f;
            }
        }
        return;
    }
    if (MODE == 2 && kfn == 0.f) return;

    const float* Ap = A + ((MODE == 2) ? (size_t)ab * K * LDA : (size_t)0) + mtile * 128;
    const float* Bp = Bsrc + (size_t)n * K * PIX + p0;

    const int lkl = tid >> 5;          // 0..7
    const int lmv = (tid & 31) * 4;    // 0..124
    const bool bok = (p0 + lmv) < PIX; // PIX%4==0, lmv 4-aligned -> vector-safe

    float4 rA = *(const float4*)(Ap + (size_t)lkl * LDA + lmv);
    float4 rB = bok ? *(const float4*)(Bp + (size_t)lkl * PIX + lmv)
                    : make_float4(0.f, 0.f, 0.f, 0.f);
    *(float4*)&As[0][lkl][lmv] = rA;
    *(float4*)&Bs[0][lkl][lmv] = rB;
    __syncthreads();

    u64 acc2[8][4];
#pragma unroll
    for (int i = 0; i < 8; i++)
#pragma unroll
        for (int j = 0; j < 4; j++) acc2[i][j] = 0ull;

#pragma unroll 1
    for (int kt = 0; kt < K/8; kt++) {
        const int cur = kt & 1;
        if (kt < K/8 - 1) {
            const int k1 = (kt + 1) * 8;
            rA = *(const float4*)(Ap + (size_t)(k1 + lkl) * LDA + lmv);
            rB = bok ? *(const float4*)(Bp + (size_t)(k1 + lkl) * PIX + lmv)
                     : make_float4(0.f, 0.f, 0.f, 0.f);
        }
        const float (*Ac)[128] = As[cur];
        const float (*Bc)[128] = Bs[cur];
#pragma unroll
        for (int kk = 0; kk < 8; kk++) {
            u64 ra2[8], rb2[4];
#pragma unroll
            for (int i = 0; i < 8; i++) ra2[i] = pack2_dup(Ac[kk][ty*8 + i]);
#pragma unroll
            for (int j = 0; j < 4; j++) rb2[j] = *(const u64*)&Bc[kk][tx*8 + 2*j];
#pragma unroll
            for (int i = 0; i < 8; i++)
#pragma unroll
                for (int j = 0; j < 4; j++)
                    fma2(acc2[i][j], ra2[i], rb2[j]);
        }
        if (kt < K/8 - 1) {
            const int nxt = cur ^ 1;
            *(float4*)&As[nxt][lkl][lmv] = rA;
            *(float4*)&Bs[nxt][lkl][lmv] = rB;
        }
        __syncthreads();
    }

    float acc[8][8];
#pragma unroll
    for (int i = 0; i < 8; i++)
#pragma unroll
        for (int j4 = 0; j4 < 4; j4++) {
            float2 v = unpack2(acc2[i][j4]);
            acc[i][2*j4] = v.x; acc[i][2*j4+1] = v.y;
        }

    if (MODE == 2) {
        const int a = ab >> 1, b = ab & 1;
#pragma unroll
        for (int j = 0; j < 8; j++) {
            int p = p0 + tx*8 + j;
            if (p >= PIX) continue;
            int h = p / IW, w = p - h * IW;
#pragma unroll
            for (int i = 0; i < 8; i++) {
                int o = mtile * 128 + ty*8 + i;
                size_t oidx = (((size_t)(n*256 + o) * (2*IH) + (2*h + a))
                               * (size_t)(2*IW)) + (2*w + b);
                out[oidx] = fmaxf(acc[i][j] + bias[o], 0.f);
            }
        }
    } else {
#pragma unroll
        for (int j = 0; j < 8; j++) {
            int p = p0 + tx*8 + j;
            if (p >= PIX) continue;
#pragma unroll
            for (int i = 0; i < 8; i++) {
                int o = ty*8 + i;
                if (o < NCLS)
                    out[((size_t)n * NCLS + o) * PIX + p] = acc[i][j] + bias[o];
            }
        }
    }
}

// ---------------- softmax + argmax + apply_deltas + clip ----------------
__global__ void k_head(const float* __restrict__ props) {
    int i = threadIdx.x;
    if (i >= NP) return;
    const float* lg = d_logit + i * NCLS;
    float mx = -1e30f;
    for (int j = 0; j < NCLS; j++) mx = fmaxf(mx, lg[j]);
    float s = 0.f;
    for (int j = 0; j < NCLS; j++) s += expf(lg[j] - mx);
    float inv = 1.f / s;
    float bmv = -1.f; int bc = 0;
    for (int j = 0; j < NCLS; j++) {
        float p = expf(lg[j] - mx) * inv;
        d_score[i*NCLS + j] = p;
        if (p > bmv) { bmv = p; bc = j; }
    }
    d_bests[i] = bmv;
    float p0 = props[i*4], p1 = props[i*4+1], p2 = props[i*4+2], p3 = props[i*4+3];
    float w = p2 - p0, h = p3 - p1;
    float cx = p0 + 0.5f*w, cy = p1 + 0.5f*h;
    const float* d = d_delt + i * (NCLS*4) + bc*4;
    float px = d[0]*w + cx, py = d[1]*h + cy;
    float pw = expf(d[2])*w, ph = expf(d[3])*h;
    d_boxes[i*4+0] = fminf(fmaxf(px - 0.5f*pw, 0.f), 1024.f);
    d_boxes[i*4+1] = fminf(fmaxf(py - 0.5f*ph, 0.f), 1024.f);
    d_boxes[i*4+2] = fminf(fmaxf(px + 0.5f*pw, 0.f), 1024.f);
    d_boxes[i*4+3] = fminf(fmaxf(py + 0.5f*ph, 0.f), 1024.f);
}

// ---------------- NMS + boxes/scores output ----------------
__global__ void k_nms(float* __restrict__ out) {
    __shared__ float sb[NP*4];
    __shared__ float sarea[NP];
    __shared__ float ss[NP];
    __shared__ int srank[NP];
    __shared__ int skeep[NP];
    int t = threadIdx.x;
    if (t < NP) ss[t] = d_bests[t];
    __syncthreads();
    if (t < NP) {
        float si = ss[t];
        int r = 0;
        for (int j = 0; j < NP; j++) {
            float sj = ss[j];
            r += (sj > si) || (sj == si && j < t);
        }
        srank[t] = r;
        float b0 = d_boxes[t*4],   b1 = d_boxes[t*4+1];
        float b2 = d_boxes[t*4+2], b3 = d_boxes[t*4+3];
        sb[r*4+0] = b0; sb[r*4+1] = b1; sb[r*4+2] = b2; sb[r*4+3] = b3;
        sarea[r] = fmaxf(b2-b0, 0.f) * fmaxf(b3-b1, 0.f);
    }
    __syncthreads();
    for (int i = 0; i < NP; i++) {
        int sup = 0;
        if (t < i && skeep[t]) {
            float xx1 = fmaxf(sb[i*4+0], sb[t*4+0]);
            float yy1 = fmaxf(sb[i*4+1], sb[t*4+1]);
            float xx2 = fminf(sb[i*4+2], sb[t*4+2]);
            float yy2 = fminf(sb[i*4+3], sb[t*4+3]);
            float inter = fmaxf(xx2-xx1, 0.f) * fmaxf(yy2-yy1, 0.f);
            float iou = inter / (sarea[i] + sarea[t] - inter + 1e-9f);
            sup = iou > 0.5f;
        }
        int any = __syncthreads_or(sup);
        if (t == 0) skeep[i] = !any;
        __syncthreads();
    }
    if (t < NP) {
        float kfi = skeep[srank[t]] ? 1.f : 0.f;
        d_keepf[t] = kfi;
        out[t*4+0] = d_boxes[t*4+0]*kfi;
        out[t*4+1] = d_boxes[t*4+1]*kfi;
        out[t*4+2] = d_boxes[t*4+2]*kfi;
        out[t*4+3] = d_boxes[t*4+3]*kfi;
        for (int j = 0; j < NCLS; j++)
            out[NP*4 + t*NCLS + j] = d_score[t*NCLS + j]*kfi;
    }
}

// ---------------- launch ----------------
extern "C" void kernel_launch(void* const* d_in, const int* in_sizes, int n_in,
                              void* d_out, int out_size) {
    const float* feature = (const float*)d_in[0];
    const float* props   = (const float*)d_in[1];
    const float* w1      = (const float*)d_in[2];
    const float* b1      = (const float*)d_in[3];
    const float* w2      = (const float*)d_in[4];
    const float* b2      = (const float*)d_in[5];
    const float* w_box   = (const float*)d_in[6];
    const float* b_box   = (const float*)d_in[7];
    const float* w_cls   = (const float*)d_in[8];
    const float* b_cls   = (const float*)d_in[9];
    const float* wt1     = (const float*)d_in[10];
    const float* bt1     = (const float*)d_in[11];
    const float* wt2     = (const float*)d_in[12];
    const float* bt2     = (const float*)d_in[13];
    const float* wm      = (const float*)d_in[14];
    const float* bm      = (const float*)d_in[15];
    float* out = (float*)d_out;

    static float *roi7 = nullptr, *part, *h1, *h2, *delt, *logit;
    static float *roi14, *m1, *m2, *wr1, *wr2, *wmT;
    if (!roi7) {   // one-time, allocation-free symbol resolution
        cudaGetSymbolAddress((void**)&roi7,  d_roi7);
        cudaGetSymbolAddress((void**)&part,  d_part);
        cudaGetSymbolAddress((void**)&h1,    d_h1);
        cudaGetSymbolAddress((void**)&h2,    d_h2);
        cudaGetSymbolAddress((void**)&delt,  d_delt);
        cudaGetSymbolAddress((void**)&logit, d_logit);
        cudaGetSymbolAddress((void**)&roi14, d_roi14);
        cudaGetSymbolAddress((void**)&m1,    d_m1);
        cudaGetSymbolAddress((void**)&m2,    d_m2);
        cudaGetSymbolAddress((void**)&wr1,   d_wr1);
        cudaGetSymbolAddress((void**)&wr2,   d_wr2);
        cudaGetSymbolAddress((void**)&wmT,   d_wmT);
    }

    k_transpose<<<dim3(2048, 8), dim3(32, 8)>>>(feature);
    k_repack<<<1088, 256>>>(wt1, wt2, wm);
    k_roi<7, 0><<<dim3(NP, 49), 256>>>(props, roi7);

    // FC1: 1024 cols, 200 rows, K=12544, split-K 16 x 784
    k_skgemm<<<dim3(8, 2, 16), 256>>>(w1, 1024, 1024, roi7, 12544, 784, part, 1024);
    k_reduce<<<800, 256>>>(part, b1, h1, NP*1024, 1024, 16, 1);
    // FC2: K=1024, split 8 x 128
    k_skgemm<<<dim3(8, 2, 8), 256>>>(w2, 1024, 1024, h1, 1024, 128, part, 1024);
    k_reduce<<<800, 256>>>(part, b2, h2, NP*1024, 1024, 8, 1);
    // box head
    k_skgemm<<<dim3(3, 2, 8), 256>>>(w_box, NCLS*4, NCLS*4, h2, 1024, 128, part, NCLS*4);
    k_reduce<<<(NP*NCLS*4 + 255)/256, 256>>>(part, b_box, delt, NP*NCLS*4, NCLS*4, 8, 0);
    // cls head
    k_skgemm<<<dim3(1, 2, 8), 256>>>(w_cls, NCLS, NCLS, h2, 1024, 128, part, NCLS);
    k_reduce<<<(NP*NCLS + 255)/256, 256>>>(part, b_cls, logit, NP*NCLS, NCLS, 8, 0);

    k_head<<<1, 256>>>(props);
    k_nms<<<1, 256>>>(out);

    k_roi<14, 1><<<dim3(NP, 196), 256>>>(nullptr, roi14);

    // deconv1: per-n tiles, z = n*4 + ab
    k_pgemm<2, 196, 14><<<dim3(2, 2, NP*4), 256>>>(wr1, roi14, bt1, m1);
    // deconv2
    k_pgemm<2, 784, 28><<<dim3(2, 7, NP*4), 256>>>(wr2, m1, bt2, m2);
    // mask head (writes/zero-fills every mask output element)
    k_pgemm<3, 3136, 56><<<dim3(1, 25, NP), 256>>>(wmT, m2, bm, out + NP*4 + NP*NCLS);
}